// round 11
// baseline (speedup 1.0000x reference)
#include <cuda_runtime.h>

#define C     62
#define FIN   512
#define FOUT  256
#define KCH   5
#define NCLS  2
#define BATCH 2048
#define REDN  (C*FIN)     // 31744
#define CFOUT (C*FOUT)    // 15872
#define NE    (C*C)       // 3844
#define PREB  128         // precompute blocks; dispatched first -> wave-1 resident
#define NUNITS 3968       // main work units (31 chunks x 128 batch-groups)

// ---------------- scratch (device globals, no allocation) ----------------
__device__ float d_G[NCLS*C*KCH*FOUT];              // [(n*62+i)*1280 + k*256 + f]
__device__ __align__(16) float d_Mf[REDN*NCLS];     // collapsed matrix, [(i*512+j)*2 + n]
__device__ __align__(128) unsigned d_bar[4][32];    // each flag on its own 128B line

// grid barrier among the PREB precompute blocks (all wave-1 resident -> safe)
__device__ __forceinline__ void gbar(int idx) {
    __syncthreads();
    if (threadIdx.x == 0) {
        __threadfence();
        atomicAdd(&d_bar[idx][0], 1u);
        while (((volatile unsigned*)&d_bar[idx][0])[0] < (unsigned)PREB) __nanosleep(32);
        __threadfence();
    }
    __syncthreads();
}

// ---------------- precompute path (noinline to protect stream-path registers) ----
__device__ __noinline__ void do_pre(
        int blk, int tid, char* sm_raw,
        const float* __restrict__ coord, const float* __restrict__ w1,
        const float* __restrict__ b1, const float* __restrict__ w2,
        const float* __restrict__ b2, const float* __restrict__ chebW,
        const float* __restrict__ chebb, const float* __restrict__ convw,
        const float* __restrict__ convb, const float* __restrict__ fcw,
        const float* __restrict__ fcb, float* __restrict__ out) {

    // ======== Phase B: blocks 0-61 do MLP+Laplacian+Chebyshev+G locally ========
    if (blk < C) {
        struct SB { float L[C][C+1]; float dis[C]; float Tc[KCH][C]; };
        SB& s = *(SB*)sm_raw;
        int i = blk;

        // adjacency MLP + threshold straight into smem (16 entries per thread)
        float b2v = b2[0];
        for (int e = tid; e < NE; e += 256) {
            int c1 = e / C, c2 = e % C;
            const float* cd = coord + e*4;
            float d0 = cd[0], d1 = cd[1], d2 = cd[2], d3 = cd[3];
            float acc = b2v;
            #pragma unroll 8
            for (int h = 0; h < 64; h++) {
                float t = d0*w1[h] + d1*w1[64+h] + d2*w1[128+h] + d3*w1[192+h] + b1[h];
                acc += fmaxf(t, 0.0f) * w2[h];
            }
            s.L[c1][c2] = (c1 != c2 && acc > 0.1f) ? acc : 0.0f;
        }
        __syncthreads();
        if (tid < C) {
            float sum = 0.0f;
            #pragma unroll
            for (int j = 0; j < C; j++) sum += s.L[tid][j];
            s.dis[tid] = (sum > 0.0f) ? (1.0f / sqrtf(sum)) : 0.0f;
        }
        __syncthreads();
        for (int e = tid; e < NE; e += 256) {
            int r = e / C, c = e % C;
            s.L[r][c] = -(s.dis[r] * s.L[r][c] * s.dis[c]);
        }
        __syncthreads();
        if (tid < C) {
            s.Tc[0][tid] = (tid == i) ? 1.0f : 0.0f;
            s.Tc[1][tid] = s.L[tid][i];
        }
        __syncthreads();
        for (int k = 2; k < KCH; k++) {
            float v = 0.0f;
            if (tid < C) {
                float sum = 0.0f;
                #pragma unroll
                for (int j = 0; j < C; j++) sum += s.L[tid][j] * s.Tc[k-1][j];
                v = 2.0f*sum - s.Tc[k-2][tid];
            }
            __syncthreads();
            if (tid < C) s.Tc[k][tid] = v;
            __syncthreads();
        }
        // G for this column: f = tid
        int f = tid;
        float a00=0,a01=0,a10=0,a11=0,a20=0,a21=0,a30=0,a31=0,a40=0,a41=0;
        const float2* fw2 = (const float2*)fcw;
        #pragma unroll
        for (int c = 0; c < C; c++) {
            float2 w = fw2[c*FOUT + f];
            float t0 = s.Tc[0][c], t1 = s.Tc[1][c], t2 = s.Tc[2][c],
                  t3 = s.Tc[3][c], t4 = s.Tc[4][c];
            a00 += t0*w.x; a01 += t0*w.y;
            a10 += t1*w.x; a11 += t1*w.y;
            a20 += t2*w.x; a21 += t2*w.y;
            a30 += t3*w.x; a31 += t3*w.y;
            a40 += t4*w.x; a41 += t4*w.y;
        }
        float* g0 = d_G + (0*C + i)*(KCH*FOUT) + f;
        float* g1 = d_G + (1*C + i)*(KCH*FOUT) + f;
        g0[0*FOUT] = a00; g1[0*FOUT] = a01;
        g0[1*FOUT] = a10; g1[1*FOUT] = a11;
        g0[2*FOUT] = a20; g1[2*FOUT] = a21;
        g0[3*FOUT] = a30; g1[3*FOUT] = a31;
        g0[4*FOUT] = a40; g1[4*FOUT] = a41;
    } else {
        // blocks 62-127: zero Mf (grid-stride over 66 blocks)
        for (int zi = (blk - C)*256 + tid; zi < (REDN*NCLS)/4; zi += 66*256)
            ((float4*)d_Mf)[zi] = make_float4(0.f, 0.f, 0.f, 0.f);
        if (blk == C) {
            // const[n] = cw*sum cheb_b[f]*fcw[cf,n] + cb*sum fcw[cf,n] + fcb[n]; init out
            float* red = (float*)sm_raw;
            float s0 = 0.f, s1 = 0.f, t0 = 0.f, t1 = 0.f;
            for (int cf = tid; cf < CFOUT; cf += 256) {
                float w0 = fcw[cf*2], w1v = fcw[cf*2 + 1];
                float bb = chebb[cf & 255];
                s0 += w0; s1 += w1v; t0 += bb*w0; t1 += bb*w1v;
            }
            red[tid] = s0; red[256+tid] = s1; red[512+tid] = t0; red[768+tid] = t1;
            __syncthreads();
            for (int off = 128; off > 0; off >>= 1) {
                if (tid < off) {
                    red[tid]     += red[tid+off];
                    red[256+tid] += red[256+tid+off];
                    red[512+tid] += red[512+tid+off];
                    red[768+tid] += red[768+tid+off];
                }
                __syncthreads();
            }
            if (tid == 0) {
                float cw = convw[0], cb = convb[0];
                red[1024] = cw*red[512] + cb*red[0]   + fcb[0];
                red[1025] = cw*red[768] + cb*red[256] + fcb[1];
            }
            __syncthreads();
            float2 cv = make_float2(red[1024], red[1025]);
            float2* out2 = (float2*)out;
            for (int b = tid; b < BATCH; b += 256) out2[b] = cv;
        }
    }
    gbar(0);

    // ======== Phase C: Mf GEMM, 128 blocks = 16 tiles (8j x 2n) x K-split 8 ========
    // 64x64 tile, 4x4 microtile, kf-chunks of 32; atomic accumulate into zeroed Mf.
    {
        struct SC { float Gs[32][68]; float Ws[32][68]; };
        SC& s = *(SC*)sm_raw;
        int part  = blk >> 4;             // 0..7 -> kf chunks [part*5, part*5+5)
        int tile  = blk & 15;
        int jbase = (tile & 7) * 64;
        int n     = tile >> 3;

        int tx = tid & 15, ty = tid >> 4;
        int r4 = ty*4, j4 = tx*4;
        float acc[4][4] = {};
        int kk  = tid & 31;
        int il0 = tid >> 5;               // 0..7

        for (int kc = part*5; kc < part*5 + 5; kc++) {
            int kf0 = kc*32;
            int k   = kf0 >> 8;
            int f0  = kf0 & 255;
            #pragma unroll
            for (int p = 0; p < 8; p++) {
                int i = il0 + p*8;        // 0..63
                s.Gs[kk][i] = (i < C) ? d_G[(n*C + i)*(KCH*FOUT) + kf0 + kk] : 0.0f;
                s.Ws[kk][i] = chebW[k*(FIN*FOUT) + (jbase + i)*FOUT + f0 + kk];
            }
            __syncthreads();
            #pragma unroll
            for (int q = 0; q < 32; q++) {
                float4 g = *(const float4*)&s.Gs[q][r4];
                float4 w = *(const float4*)&s.Ws[q][j4];
                float gg[4] = {g.x, g.y, g.z, g.w};
                float ww[4] = {w.x, w.y, w.z, w.w};
                #pragma unroll
                for (int a = 0; a < 4; a++)
                    #pragma unroll
                    for (int b = 0; b < 4; b++)
                        acc[a][b] += gg[a]*ww[b];
            }
            __syncthreads();
        }

        float cw = convw[0];
        #pragma unroll
        for (int a = 0; a < 4; a++) {
            int i = r4 + a;
            if (i >= C) continue;
            #pragma unroll
            for (int b = 0; b < 4; b++) {
                int j = jbase + j4 + b;
                atomicAdd(&d_Mf[(i*FIN + j)*NCLS + n], cw*acc[a][b]);
            }
        }
    }
    __threadfence();
    __syncthreads();
    if (tid == 0) atomicAdd(&d_bar[2][0], 1u);      // ready++
}

// ---------------- single fused kernel ----------------
__global__ void __launch_bounds__(256) k_all(
        const float* __restrict__ x,
        const float* __restrict__ coord, const float* __restrict__ w1,
        const float* __restrict__ b1, const float* __restrict__ w2,
        const float* __restrict__ b2, const float* __restrict__ chebW,
        const float* __restrict__ chebb, const float* __restrict__ convw,
        const float* __restrict__ convb, const float* __restrict__ fcw,
        const float* __restrict__ fcb, float* __restrict__ out) {
    __shared__ __align__(16) char sm_raw[17408];
    int tid = threadIdx.x;
    int blk = blockIdx.x;
    int unit;

    if (blk < PREB) {
        unit = NUNITS - PREB + blk;
        do_pre(blk, tid, sm_raw, coord, w1, b1, w2, b2, chebW,
               chebb, convw, convb, fcw, fcb, out);
    } else {
        unit = blk - PREB;
        // prefetch our x slice into L2 while the precompute runs (wave-1 blocks only)
        if (((volatile unsigned*)&d_bar[2][0])[0] < (unsigned)PREB) {
            int chunk = unit >> 7;
            int bg    = unit & 127;
            int idx0  = chunk << 10;
            int b0q   = bg * 16;
            #pragma unroll
            for (int p = 0; p < 2; p++) {
                int line = tid + p*256;          // 512 lines of 128B = 64KB
                int row  = line >> 5;            // batch row 0..15
                int off  = (line & 31) << 5;     // float offset in 1024-chunk
                const float* addr = x + (size_t)(b0q + row)*REDN + idx0 + off;
                asm volatile("prefetch.global.L2 [%0];" :: "l"(addr));
            }
        }
    }

    // ---- wait until Mf is complete ----
    if (tid == 0) {
        while (((volatile unsigned*)&d_bar[2][0])[0] < (unsigned)PREB) __nanosleep(64);
        __threadfence();
    }
    __syncthreads();

    // ======== main pass: out[b,n] += sum over this unit's 1024-idx chunk ========
    {
        int chunk = unit >> 7;
        int bg    = unit & 127;
        int idx0  = chunk << 10;

        float4* Ms4 = (float4*)sm_raw;           // 1024 idx * 2 classes = 8KB
        const float4* Mf4 = (const float4*)(d_Mf + idx0*2);
        Ms4[tid]       = Mf4[tid];
        Ms4[tid + 256] = Mf4[tid + 256];
        __syncthreads();

        int warp = tid >> 5, lane = tid & 31;
        int b0 = bg*16 + warp*2;
        const float4* xa = (const float4*)(x + (size_t)b0*REDN + idx0);
        const float4* xb = (const float4*)(x + (size_t)(b0+1)*REDN + idx0);

        float a0 = 0.f, a1 = 0.f, c0 = 0.f, c1 = 0.f;
        #pragma unroll
        for (int it = 0; it < 8; it++) {
            int t = lane + it*32;
            float4 xv = xa[t];
            float4 yv = xb[t];
            float4 q0 = Ms4[2*t];
            float4 q1 = Ms4[2*t + 1];
            a0 += xv.x*q0.x + xv.y*q0.z + xv.z*q1.x + xv.w*q1.z;
            a1 += xv.x*q0.y + xv.y*q0.w + xv.z*q1.y + xv.w*q1.w;
            c0 += yv.x*q0.x + yv.y*q0.z + yv.z*q1.x + yv.w*q1.z;
            c1 += yv.x*q0.y + yv.y*q0.w + yv.z*q1.y + yv.w*q1.w;
        }
        #pragma unroll
        for (int off = 16; off; off >>= 1) {
            a0 += __shfl_down_sync(0xFFFFFFFFu, a0, off);
            a1 += __shfl_down_sync(0xFFFFFFFFu, a1, off);
            c0 += __shfl_down_sync(0xFFFFFFFFu, c0, off);
            c1 += __shfl_down_sync(0xFFFFFFFFu, c1, off);
        }
        if (lane == 0) {
            float* o0 = &out[b0*2];
            atomicAdd(o0,     a0);
            atomicAdd(o0 + 1, a1);
            atomicAdd(o0 + 2, c0);
            atomicAdd(o0 + 3, c1);
        }
    }

    // ---- completion: last block resets counters for the next graph replay ----
    __syncthreads();
    if (tid == 0) {
        unsigned p = atomicAdd(&d_bar[3][0], 1u);
        if (p == (unsigned)(NUNITS - 1)) {
            d_bar[0][0] = 0; d_bar[1][0] = 0; d_bar[2][0] = 0; d_bar[3][0] = 0;
            __threadfence();
        }
    }
}

// ---------------- launcher ----------------
extern "C" void kernel_launch(void* const* d_in, const int* in_sizes, int n_in,
                              void* d_out, int out_size) {
    const float* x      = (const float*)d_in[0];
    const float* coord  = (const float*)d_in[1];
    const float* adj_w1 = (const float*)d_in[2];
    const float* adj_b1 = (const float*)d_in[3];
    const float* adj_w2 = (const float*)d_in[4];
    const float* adj_b2 = (const float*)d_in[5];
    const float* cheb_W = (const float*)d_in[6];
    const float* cheb_b = (const float*)d_in[7];
    const float* conv_w = (const float*)d_in[8];
    const float* conv_b = (const float*)d_in[9];
    const float* fc_w   = (const float*)d_in[10];
    const float* fc_b   = (const float*)d_in[11];
    float* out = (float*)d_out;

    k_all<<<NUNITS, 256>>>(x, coord, adj_w1, adj_b1, adj_w2, adj_b2,
                           cheb_W, cheb_b, conv_w, conv_b, fc_w, fc_b, out);
}

// round 14
// speedup vs baseline: 1.3017x; 1.3017x over previous
#include <cuda_runtime.h>

#define C     62
#define FIN   512
#define FOUT  256
#define KCH   5
#define NCLS  2
#define BATCH 2048
#define REDN  (C*FIN)     // 31744
#define CFOUT (C*FOUT)    // 15872
#define NE    (C*C)       // 3844
#define PREB  128         // precompute blocks; dispatched first -> wave-1 resident
#define NUNITS 3968       // main work units (31 chunks x 128 batch-groups)

// ---------------- scratch (device globals, no allocation) ----------------
__device__ float d_A[NE];                           // thresholded adjacency
__device__ float d_G[NCLS*C*KCH*FOUT];              // [(n*62+i)*1280 + k*256 + f]
__device__ __align__(16) float d_Mf[REDN*NCLS];     // collapsed matrix, [(i*512+j)*2 + n]
__device__ __align__(128) unsigned d_bar[4][32];    // each flag on its own 128B line

// grid barrier among the PREB precompute blocks (all wave-1 resident -> safe)
__device__ __forceinline__ void gbar(int idx) {
    __syncthreads();
    if (threadIdx.x == 0) {
        __threadfence();
        atomicAdd(&d_bar[idx][0], 1u);
        while (((volatile unsigned*)&d_bar[idx][0])[0] < (unsigned)PREB) __nanosleep(32);
        __threadfence();
    }
    __syncthreads();
}

// ---------------- single fused kernel ----------------
__global__ void __launch_bounds__(256) k_all(
        const float* __restrict__ x,
        const float* __restrict__ coord, const float* __restrict__ w1,
        const float* __restrict__ b1, const float* __restrict__ w2,
        const float* __restrict__ b2, const float* __restrict__ chebW,
        const float* __restrict__ chebb, const float* __restrict__ convw,
        const float* __restrict__ convb, const float* __restrict__ fcw,
        const float* __restrict__ fcb, float* __restrict__ out) {
    __shared__ __align__(16) char sm_raw[17408];
    int tid = threadIdx.x;
    int blk = blockIdx.x;
    int unit;

    if (blk < PREB) {
        unit = NUNITS - PREB + blk;

        // ======== Phase A: Mf zero + adjacency MLP (blocks 0-15) + const/out (block 16)
        {
            int zi = blk*256 + tid;
            if (zi < (REDN*NCLS)/4)
                ((float4*)d_Mf)[zi] = make_float4(0.f, 0.f, 0.f, 0.f);
        }
        {
            int e = blk*256 + tid;
            if (e < NE) {
                int c1 = e / C, c2 = e % C;
                const float* cd = coord + e*4;
                float d0 = cd[0], d1 = cd[1], d2 = cd[2], d3 = cd[3];
                float acc = b2[0];
                #pragma unroll 8
                for (int h = 0; h < 64; h++) {
                    float t = d0*w1[h] + d1*w1[64+h] + d2*w1[128+h] + d3*w1[192+h] + b1[h];
                    acc += fmaxf(t, 0.0f) * w2[h];
                }
                d_A[e] = (c1 != c2 && acc > 0.1f) ? acc : 0.0f;
            }
        }
        if (blk == 16) {
            float* red = (float*)sm_raw;           // 1026 floats
            float s0 = 0.f, s1 = 0.f, t0 = 0.f, t1 = 0.f;
            for (int cf = tid; cf < CFOUT; cf += 256) {
                float w0 = fcw[cf*2], w1v = fcw[cf*2 + 1];
                float bb = chebb[cf & 255];
                s0 += w0; s1 += w1v; t0 += bb*w0; t1 += bb*w1v;
            }
            red[tid] = s0; red[256+tid] = s1; red[512+tid] = t0; red[768+tid] = t1;
            __syncthreads();
            for (int off = 128; off > 0; off >>= 1) {
                if (tid < off) {
                    red[tid]     += red[tid+off];
                    red[256+tid] += red[256+tid+off];
                    red[512+tid] += red[512+tid+off];
                    red[768+tid] += red[768+tid+off];
                }
                __syncthreads();
            }
            if (tid == 0) {
                float cw = convw[0], cb = convb[0];
                red[1024] = cw*red[512] + cb*red[0]   + fcb[0];
                red[1025] = cw*red[768] + cb*red[256] + fcb[1];
            }
            __syncthreads();
            float2 cv = make_float2(red[1024], red[1025]);
            float2* out2 = (float2*)out;
            for (int b = tid; b < BATCH; b += 256) out2[b] = cv;
        }
        gbar(0);

        // ======== Phase B: per-column Chebyshev + G (blocks 0-61) ========
        if (blk < C) {
            struct SB { float L[C][C+1]; float dis[C]; float Tc[KCH][C]; };
            SB& s = *(SB*)sm_raw;
            int i = blk;
            for (int e = tid; e < NE; e += 256)
                s.L[e / C][e % C] = d_A[e];
            __syncthreads();
            if (tid < C) {
                float sum = 0.0f;
                #pragma unroll
                for (int j = 0; j < C; j++) sum += s.L[tid][j];
                s.dis[tid] = (sum > 0.0f) ? (1.0f / sqrtf(sum)) : 0.0f;
            }
            __syncthreads();
            for (int e = tid; e < NE; e += 256) {
                int r = e / C, c = e % C;
                s.L[r][c] = -(s.dis[r] * s.L[r][c] * s.dis[c]);
            }
            __syncthreads();
            if (tid < C) {
                s.Tc[0][tid] = (tid == i) ? 1.0f : 0.0f;
                s.Tc[1][tid] = s.L[tid][i];
            }
            __syncthreads();
            for (int k = 2; k < KCH; k++) {
                float v = 0.0f;
                if (tid < C) {
                    float sum = 0.0f;
                    #pragma unroll
                    for (int j = 0; j < C; j++) sum += s.L[tid][j] * s.Tc[k-1][j];
                    v = 2.0f*sum - s.Tc[k-2][tid];
                }
                __syncthreads();
                if (tid < C) s.Tc[k][tid] = v;
                __syncthreads();
            }
            int f = tid;
            float a00=0,a01=0,a10=0,a11=0,a20=0,a21=0,a30=0,a31=0,a40=0,a41=0;
            const float2* fw2 = (const float2*)fcw;
            #pragma unroll
            for (int c = 0; c < C; c++) {
                float2 w = fw2[c*FOUT + f];
                float t0 = s.Tc[0][c], t1 = s.Tc[1][c], t2 = s.Tc[2][c],
                      t3 = s.Tc[3][c], t4 = s.Tc[4][c];
                a00 += t0*w.x; a01 += t0*w.y;
                a10 += t1*w.x; a11 += t1*w.y;
                a20 += t2*w.x; a21 += t2*w.y;
                a30 += t3*w.x; a31 += t3*w.y;
                a40 += t4*w.x; a41 += t4*w.y;
            }
            float* g0 = d_G + (0*C + i)*(KCH*FOUT) + f;
            float* g1 = d_G + (1*C + i)*(KCH*FOUT) + f;
            g0[0*FOUT] = a00; g1[0*FOUT] = a01;
            g0[1*FOUT] = a10; g1[1*FOUT] = a11;
            g0[2*FOUT] = a20; g1[2*FOUT] = a21;
            g0[3*FOUT] = a30; g1[3*FOUT] = a31;
            g0[4*FOUT] = a40; g1[4*FOUT] = a41;
        }
        gbar(1);

        // ======== Phase C: Mf GEMM, 128 blocks = 16 tiles (8j x 2n) x K-split 8 ======
        // 64x64 tile, 4x4 microtile, kf-chunks of 32; atomic accumulate into zeroed Mf.
        {
            struct SC { float Gs[32][68]; float Ws[32][68]; };
            SC& s = *(SC*)sm_raw;
            int part  = blk >> 4;             // 0..7 -> kf chunks [part*5, part*5+5)
            int tile  = blk & 15;
            int jbase = (tile & 7) * 64;
            int n     = tile >> 3;

            int tx = tid & 15, ty = tid >> 4;
            int r4 = ty*4, j4 = tx*4;
            float acc[4][4] = {};
            int kk  = tid & 31;
            int il0 = tid >> 5;               // 0..7

            for (int kc = part*5; kc < part*5 + 5; kc++) {
                int kf0 = kc*32;
                int k   = kf0 >> 8;
                int f0  = kf0 & 255;
                #pragma unroll
                for (int p = 0; p < 8; p++) {
                    int i = il0 + p*8;        // 0..63
                    s.Gs[kk][i] = (i < C) ? d_G[(n*C + i)*(KCH*FOUT) + kf0 + kk] : 0.0f;
                    s.Ws[kk][i] = chebW[k*(FIN*FOUT) + (jbase + i)*FOUT + f0 + kk];
                }
                __syncthreads();
                #pragma unroll
                for (int q = 0; q < 32; q++) {
                    float4 g = *(const float4*)&s.Gs[q][r4];
                    float4 w = *(const float4*)&s.Ws[q][j4];
                    float gg[4] = {g.x, g.y, g.z, g.w};
                    float ww[4] = {w.x, w.y, w.z, w.w};
                    #pragma unroll
                    for (int a = 0; a < 4; a++)
                        #pragma unroll
                        for (int b = 0; b < 4; b++)
                            acc[a][b] += gg[a]*ww[b];
                }
                __syncthreads();
            }

            float cw = convw[0];
            #pragma unroll
            for (int a = 0; a < 4; a++) {
                int i = r4 + a;
                if (i >= C) continue;
                #pragma unroll
                for (int b = 0; b < 4; b++) {
                    int j = jbase + j4 + b;
                    atomicAdd(&d_Mf[(i*FIN + j)*NCLS + n], cw*acc[a][b]);
                }
            }
        }
        __threadfence();
        __syncthreads();
        if (tid == 0) atomicAdd(&d_bar[2][0], 1u);      // ready++
    } else {
        unit = blk - PREB;
        // prefetch our x slice into L2 while the precompute runs (wave-1 blocks only)
        if (((volatile unsigned*)&d_bar[2][0])[0] < (unsigned)PREB) {
            int chunk = unit >> 7;
            int bg    = unit & 127;
            int idx0  = chunk << 10;
            int b0q   = bg * 16;
            #pragma unroll
            for (int p = 0; p < 2; p++) {
                int line = tid + p*256;          // 512 lines of 128B = 64KB
                int row  = line >> 5;            // batch row 0..15
                int off  = (line & 31) << 5;     // float offset in 1024-chunk
                const float* addr = x + (size_t)(b0q + row)*REDN + idx0 + off;
                asm volatile("prefetch.global.L2 [%0];" :: "l"(addr));
            }
        }
    }

    // ---- wait until Mf is complete (low-traffic poll: sleep-dominant) ----
    if (tid == 0) {
        while (((volatile unsigned*)&d_bar[2][0])[0] < (unsigned)PREB) __nanosleep(200);
        __threadfence();
    }
    __syncthreads();

    // ======== main pass: out[b,n] += sum over this unit's 1024-idx chunk ========
    {
        int chunk = unit >> 7;
        int bg    = unit & 127;
        int idx0  = chunk << 10;

        float4* Ms4 = (float4*)sm_raw;           // 1024 idx * 2 classes = 8KB
        const float4* Mf4 = (const float4*)(d_Mf + idx0*2);
        Ms4[tid]       = Mf4[tid];
        Ms4[tid + 256] = Mf4[tid + 256];
        __syncthreads();

        int warp = tid >> 5, lane = tid & 31;
        int b0 = bg*16 + warp*2;
        const float4* xa = (const float4*)(x + (size_t)b0*REDN + idx0);
        const float4* xb = (const float4*)(x + (size_t)(b0+1)*REDN + idx0);

        float a0 = 0.f, a1 = 0.f, c0 = 0.f, c1 = 0.f;
        #pragma unroll
        for (int it = 0; it < 8; it++) {
            int t = lane + it*32;
            float4 xv = xa[t];
            float4 yv = xb[t];
            float4 q0 = Ms4[2*t];
            float4 q1 = Ms4[2*t + 1];
            a0 += xv.x*q0.x + xv.y*q0.z + xv.z*q1.x + xv.w*q1.z;
            a1 += xv.x*q0.y + xv.y*q0.w + xv.z*q1.y + xv.w*q1.w;
            c0 += yv.x*q0.x + yv.y*q0.z + yv.z*q1.x + yv.w*q1.z;
            c1 += yv.x*q0.y + yv.y*q0.w + yv.z*q1.y + yv.w*q1.w;
        }
        #pragma unroll
        for (int off = 16; off; off >>= 1) {
            a0 += __shfl_down_sync(0xFFFFFFFFu, a0, off);
            a1 += __shfl_down_sync(0xFFFFFFFFu, a1, off);
            c0 += __shfl_down_sync(0xFFFFFFFFu, c0, off);
            c1 += __shfl_down_sync(0xFFFFFFFFu, c1, off);
        }
        if (lane == 0) {
            float* o0 = &out[b0*2];
            atomicAdd(o0,     a0);
            atomicAdd(o0 + 1, a1);
            atomicAdd(o0 + 2, c0);
            atomicAdd(o0 + 3, c1);
        }
    }

    // ---- completion: last block resets counters for the next graph replay ----
    __syncthreads();
    if (tid == 0) {
        unsigned p = atomicAdd(&d_bar[3][0], 1u);
        if (p == (unsigned)(NUNITS - 1)) {
            d_bar[0][0] = 0; d_bar[1][0] = 0; d_bar[2][0] = 0; d_bar[3][0] = 0;
            __threadfence();
        }
    }
}

// ---------------- launcher ----------------
extern "C" void kernel_launch(void* const* d_in, const int* in_sizes, int n_in,
                              void* d_out, int out_size) {
    const float* x      = (const float*)d_in[0];
    const float* coord  = (const float*)d_in[1];
    const float* adj_w1 = (const float*)d_in[2];
    const float* adj_b1 = (const float*)d_in[3];
    const float* adj_w2 = (const float*)d_in[4];
    const float* adj_b2 = (const float*)d_in[5];
    const float* cheb_W = (const float*)d_in[6];
    const float* cheb_b = (const float*)d_in[7];
    const float* conv_w = (const float*)d_in[8];
    const float* conv_b = (const float*)d_in[9];
    const float* fc_w   = (const float*)d_in[10];
    const float* fc_b   = (const float*)d_in[11];
    float* out = (float*)d_out;

    k_all<<<NUNITS, 256>>>(x, coord, adj_w1, adj_b1, adj_w2, adj_b2,
                           cheb_W, cheb_b, conv_w, conv_b, fc_w, fc_b, out);
}